// round 2
// baseline (speedup 1.0000x reference)
#include <cuda_runtime.h>
#include <math.h>

#define NN 100000
#define NE 1600000
#define H  128
#define NG 128

// ---------------- scratch (device globals; no allocation allowed) ----------
__device__ float d_h[(size_t)NN * H];
__device__ float d_agg[(size_t)NN * H];
__device__ float d_gi[(size_t)NN * 3 * H];
__device__ float d_gh[(size_t)NN * 3 * H];
__device__ float d_dense[(size_t)NN * H];
__device__ float d_gmax[(size_t)NG * H];

// ---------------- gather: h = emb[x] ---------------------------------------
__global__ void gather_embed(const int* __restrict__ x,
                             const float* __restrict__ emb) {
    int idx = blockIdx.x * blockDim.x + threadIdx.x;   // NN*32 threads
    if (idx >= NN * 32) return;
    int n = idx >> 5, c = idx & 31;
    int tok = x[n];
    float4 v = *(const float4*)&emb[(size_t)tok * H + c * 4];
    *(float4*)&d_h[(size_t)n * H + c * 4] = v;
}

// ---------------- zero agg --------------------------------------------------
__global__ void zero_agg() {
    int idx = blockIdx.x * blockDim.x + threadIdx.x;   // NN*H/4
    if (idx >= NN * H / 4) return;
    *(float4*)&d_agg[(size_t)idx * 4] = make_float4(0.f, 0.f, 0.f, 0.f);
}

// ---------------- scatter-add: agg[dst] += h[src] ---------------------------
__global__ void scatter_add(const int* __restrict__ ei) {
    int idx = blockIdx.x * blockDim.x + threadIdx.x;   // NE*32 threads
    if (idx >= NE * 32) return;
    int e = idx >> 5, c = idx & 31;
    int src = ei[e];
    int dst = ei[NE + e];
    float4 v = *(const float4*)&d_h[(size_t)src * H + c * 4];
    float* a = &d_agg[(size_t)dst * H + c * 4];
    atomicAdd(a + 0, v.x);
    atomicAdd(a + 1, v.y);
    atomicAdd(a + 2, v.z);
    atomicAdd(a + 3, v.w);
}

// ---------------- SGEMM: C[M,N] = A[M,128] @ W[N,128]^T + bias --------------
// BM=BN=128, full K=128 resident in smem, 256 threads, 8x8 micro-tile.
// Smem layout: row-major 128 floats/row, XOR-swizzled float4 column:
//   col4_stored = k4 ^ ((row>>3)&7)  -> conflict-free stores (permutation per
//   row) and <=2-way conflicts on fragment loads (frag row stride is 8 rows,
//   so (row>>3) differs per tx/ty group).
__global__ void sgemm_k128(const float* __restrict__ A,
                           const float* __restrict__ W,
                           const float* __restrict__ bias,
                           float* __restrict__ C,
                           int M, int N) {
    extern __shared__ float smem[];
    float* sA = smem;              // [128][128] swizzled
    float* sB = smem + 128 * 128;  // [128][128] swizzled

    const int tid  = threadIdx.x;
    const int warp = tid >> 5, lane = tid & 31;
    const int bm = blockIdx.x * 128;
    const int bn = blockIdx.y * 128;

    // load A tile (one row per warp per iter; lane = k4)
    #pragma unroll
    for (int r = warp; r < 128; r += 8) {
        int m = bm + r;
        float4 v = make_float4(0.f, 0.f, 0.f, 0.f);
        if (m < M) v = *(const float4*)&A[(size_t)m * 128 + lane * 4];
        int c4 = lane ^ ((r >> 3) & 7);
        *(float4*)&sA[r * 128 + c4 * 4] = v;
    }
    // load W tile (N is always a multiple of 128 here)
    #pragma unroll
    for (int r = warp; r < 128; r += 8) {
        int n = bn + r;
        float4 v = *(const float4*)&W[(size_t)n * 128 + lane * 4];
        int c4 = lane ^ ((r >> 3) & 7);
        *(float4*)&sB[r * 128 + c4 * 4] = v;
    }
    __syncthreads();

    const int tx = tid & 15;   // n-group: n = bn + tx*8 + j
    const int ty = tid >> 4;   // m-group: m = bm + ty*8 + i

    float acc[8][8];
    #pragma unroll
    for (int i = 0; i < 8; i++)
        #pragma unroll
        for (int j = 0; j < 8; j++) acc[i][j] = 0.f;

    #pragma unroll
    for (int k4 = 0; k4 < 32; k4++) {
        float4 b4[8];
        #pragma unroll
        for (int j = 0; j < 8; j++) {
            int r = tx * 8 + j;
            b4[j] = *(const float4*)&sB[r * 128 + (k4 ^ ((r >> 3) & 7)) * 4];
        }
        #pragma unroll
        for (int i = 0; i < 8; i++) {
            int r = ty * 8 + i;
            float4 a4 = *(const float4*)&sA[r * 128 + (k4 ^ ((r >> 3) & 7)) * 4];
            #pragma unroll
            for (int j = 0; j < 8; j++) {
                acc[i][j] += a4.x * b4[j].x;
                acc[i][j] += a4.y * b4[j].y;
                acc[i][j] += a4.z * b4[j].z;
                acc[i][j] += a4.w * b4[j].w;
            }
        }
    }

    // epilogue: add bias, store (vectorized 2x float4 per row)
    const int nbase = bn + tx * 8;
    float bsv[8];
    #pragma unroll
    for (int j = 0; j < 8; j++) bsv[j] = bias[nbase + j];

    #pragma unroll
    for (int i = 0; i < 8; i++) {
        int m = bm + ty * 8 + i;
        if (m >= M) continue;
        float4 v0 = make_float4(acc[i][0] + bsv[0], acc[i][1] + bsv[1],
                                acc[i][2] + bsv[2], acc[i][3] + bsv[3]);
        float4 v1 = make_float4(acc[i][4] + bsv[4], acc[i][5] + bsv[5],
                                acc[i][6] + bsv[6], acc[i][7] + bsv[7]);
        *(float4*)&C[(size_t)m * N + nbase]     = v0;
        *(float4*)&C[(size_t)m * N + nbase + 4] = v1;
    }
}

// ---------------- GRU elementwise update ------------------------------------
__global__ void gru_update() {
    int idx = blockIdx.x * blockDim.x + threadIdx.x;   // NN*H
    if (idx >= NN * H) return;
    int n = idx >> 7, j = idx & 127;
    const float* gi = &d_gi[(size_t)n * 384];
    const float* gh = &d_gh[(size_t)n * 384];
    float r  = 1.f / (1.f + expf(-(gi[j] + gh[j])));
    float z  = 1.f / (1.f + expf(-(gi[128 + j] + gh[128 + j])));
    float nn = tanhf(gi[256 + j] + r * gh[256 + j]);
    float ho = d_h[idx];
    d_h[idx] = (1.f - z) * nn + z * ho;
}

// ---------------- segment max ------------------------------------------------
__global__ void init_gmax() {
    int idx = blockIdx.x * blockDim.x + threadIdx.x;
    if (idx >= NG * H) return;
    ((unsigned int*)d_gmax)[idx] = 0xFF800000u;  // -inf
}

__device__ __forceinline__ void atomicMaxF(float* addr, float val) {
    if (val >= 0.f)
        atomicMax((int*)addr, __float_as_int(val));
    else
        atomicMin((unsigned int*)addr, __float_as_uint(val));
}

__global__ void seg_max(const int* __restrict__ batch) {
    int idx = blockIdx.x * blockDim.x + threadIdx.x;   // NN*H
    if (idx >= NN * H) return;
    int n = idx >> 7, j = idx & 127;
    int g = batch[n];
    atomicMaxF(&d_gmax[(size_t)g * H + j], d_dense[idx]);
}

// ---------------- classifier -------------------------------------------------
__global__ void classify(const float* __restrict__ clfW,
                         const float* __restrict__ clfb,
                         float* __restrict__ out) {
    __shared__ float red[4];
    int g = blockIdx.x;
    int t = threadIdx.x;   // 128
    float v = d_gmax[(size_t)g * H + t] * clfW[t];
    #pragma unroll
    for (int o = 16; o > 0; o >>= 1) v += __shfl_down_sync(0xffffffffu, v, o);
    if ((t & 31) == 0) red[t >> 5] = v;
    __syncthreads();
    if (t == 0) {
        float s = red[0] + red[1] + red[2] + red[3] + clfb[0];
        out[g] = 1.f / (1.f + expf(-s));
    }
}

// ---------------- launch -----------------------------------------------------
extern "C" void kernel_launch(void* const* d_in, const int* in_sizes, int n_in,
                              void* d_out, int out_size) {
    const int*   x       = (const int*)d_in[0];
    const int*   ei      = (const int*)d_in[1];
    const int*   batch   = (const int*)d_in[2];
    const float* emb     = (const float*)d_in[3];
    const float* Wih0    = (const float*)d_in[4];
    const float* Whh0    = (const float*)d_in[5];
    const float* bih0    = (const float*)d_in[6];
    const float* bhh0    = (const float*)d_in[7];
    const float* Wih1    = (const float*)d_in[8];
    const float* Whh1    = (const float*)d_in[9];
    const float* bih1    = (const float*)d_in[10];
    const float* bhh1    = (const float*)d_in[11];
    const float* denseW  = (const float*)d_in[12];
    const float* denseB  = (const float*)d_in[13];
    const float* clfW    = (const float*)d_in[14];
    const float* clfB    = (const float*)d_in[15];
    float* out = (float*)d_out;

    const int SMEM = 2 * 128 * 128 * 4;  // 128 KB
    cudaFuncSetAttribute(sgemm_k128, cudaFuncAttributeMaxDynamicSharedMemorySize, SMEM);

    // device scratch pointers (symbols referenced directly inside kernels)
    float *p_h, *p_agg, *p_gi, *p_gh, *p_dense;
    cudaGetSymbolAddress((void**)&p_h, d_h);
    cudaGetSymbolAddress((void**)&p_agg, d_agg);
    cudaGetSymbolAddress((void**)&p_gi, d_gi);
    cudaGetSymbolAddress((void**)&p_gh, d_gh);
    cudaGetSymbolAddress((void**)&p_dense, d_dense);

    const int T = 256;
    dim3 gemm_grid_gru((NN + 127) / 128, 3);
    dim3 gemm_grid_dense((NN + 127) / 128, 1);

    // h = emb[x]
    gather_embed<<<(NN * 32 + T - 1) / T, T>>>(x, emb);

    const float* Wih[2] = {Wih0, Wih1};
    const float* Whh[2] = {Whh0, Whh1};
    const float* bih[2] = {bih0, bih1};
    const float* bhh[2] = {bhh0, bhh1};

    for (int layer = 0; layer < 2; layer++) {
        zero_agg<<<(NN * H / 4 + T - 1) / T, T>>>();
        scatter_add<<<(NE * 32 + T - 1) / T, T>>>(ei);
        sgemm_k128<<<gemm_grid_gru, T, SMEM>>>(p_agg, Wih[layer], bih[layer],
                                               p_gi, NN, 384);
        sgemm_k128<<<gemm_grid_gru, T, SMEM>>>(p_h, Whh[layer], bhh[layer],
                                               p_gh, NN, 384);
        gru_update<<<(NN * H + T - 1) / T, T>>>();
    }

    // dense
    sgemm_k128<<<gemm_grid_dense, T, SMEM>>>(p_h, denseW, denseB, p_dense, NN, 128);

    // global max pool + classifier
    init_gmax<<<(NG * H + T - 1) / T, T>>>();
    seg_max<<<(NN * H + T - 1) / T, T>>>(batch);
    classify<<<NG, 128>>>(clfW, clfB, out);
}

// round 3
// speedup vs baseline: 2.8312x; 2.8312x over previous
#include <cuda_runtime.h>
#include <math.h>
#include <stdint.h>

#define NN 100000
#define NE 1600000
#define H  128
#define NG 128

// ---------------- scratch (device globals; no allocation allowed) ----------
__device__ float d_h[(size_t)NN * H];
__device__ float d_agg[(size_t)NN * H];
__device__ float d_gi[(size_t)NN * 3 * H];
__device__ float d_gh[(size_t)NN * 3 * H];
__device__ float d_dense[(size_t)NN * H];
__device__ float d_gmax[(size_t)NG * H];

// ---------------- gather: h = emb[x] ---------------------------------------
__global__ void gather_embed(const int* __restrict__ x,
                             const float* __restrict__ emb) {
    int idx = blockIdx.x * blockDim.x + threadIdx.x;   // NN*32 threads
    if (idx >= NN * 32) return;
    int n = idx >> 5, c = idx & 31;
    int tok = x[n];
    float4 v = *(const float4*)&emb[(size_t)tok * H + c * 4];
    *(float4*)&d_h[(size_t)n * H + c * 4] = v;
}

// ---------------- zero agg --------------------------------------------------
__global__ void zero_agg() {
    int idx = blockIdx.x * blockDim.x + threadIdx.x;   // NN*H/4
    if (idx >= NN * H / 4) return;
    *(float4*)&d_agg[(size_t)idx * 4] = make_float4(0.f, 0.f, 0.f, 0.f);
}

// ---------------- scatter-add: agg[dst] += h[src] (vector red) --------------
__global__ void scatter_add(const int* __restrict__ ei) {
    int idx = blockIdx.x * blockDim.x + threadIdx.x;   // NE*32 threads
    if (idx >= NE * 32) return;
    int e = idx >> 5, c = idx & 31;
    int src = __ldg(&ei[e]);
    int dst = __ldg(&ei[NE + e]);
    float4 v = *(const float4*)&d_h[(size_t)src * H + c * 4];
    float* a = &d_agg[(size_t)dst * H + c * 4];
    asm volatile("red.global.add.v4.f32 [%0], {%1,%2,%3,%4};"
                 :: "l"(a), "f"(v.x), "f"(v.y), "f"(v.z), "f"(v.w)
                 : "memory");
}

// ---------------- GEMM via packed f32x2 FMA ---------------------------------
// C[M,N] = A[M,128] @ W[N,128]^T + bias.  BM=BN=128, K=128 fully resident.
// 512 threads = 16 warps in a 4x4 warp grid; each warp owns a 32x32 tile;
// each thread a 4m x 8n (4 n-pairs) micro-tile accumulated in f32x2 regs.
//
// smem layouts (block-swizzled, 16B "blocks", one block = one k-pair):
//  sA (128 KB): row r (local m), block kp holds {A[r][2kp],A[r][2kp],
//               A[r][2kp+1],A[r][2kp+1]}  (pre-duplicated for f32x2 bcast)
//               physical block pb = kp ^ ((r>>2)&7)
//  sB (64 KB):  row n2 (n pair), block kp holds {W[2n2][2kp],W[2n2+1][2kp],
//               W[2n2][2kp+1],W[2n2+1][2kp+1]}
//               physical block pb = kp ^ (n2&31)
// So one LDS.128 yields two ready f32x2 operands; zero packing MOVs.
__global__ void __launch_bounds__(512, 1)
gemm_f32x2(const float* __restrict__ A, const float* __restrict__ W,
           const float* __restrict__ bias, float* __restrict__ C,
           int M, int N) {
    extern __shared__ float smem[];
    float* sA = smem;            // 128 rows * 256 floats
    float* sB = smem + 32768;    // 64 rows * 256 floats

    const int tid  = threadIdx.x;
    const int w    = tid >> 5, lane = tid & 31;
    const int bm   = blockIdx.x * 128;
    const int bn   = blockIdx.y * 128;

    // ---- load A, duplicate-expand, swizzled store ----
    {
        const int tf = (lane >> 2) & 1;     // store-order trick: bank-conflict-free
        #pragma unroll
        for (int it = 0; it < 8; it++) {
            int r = w + it * 16;
            int m = bm + r;
            float4 v = make_float4(0.f, 0.f, 0.f, 0.f);
            if (m < M) v = *(const float4*)&A[(size_t)m * 128 + lane * 4];
            float4 u0 = make_float4(v.x, v.x, v.y, v.y);   // kp = 2*lane
            float4 u1 = make_float4(v.z, v.z, v.w, v.w);   // kp = 2*lane+1
            int sx = (r >> 2) & 7;
            int p0 = (2 * lane + tf) ^ sx;
            int p1 = (2 * lane + 1 - tf) ^ sx;
            *(float4*)&sA[r * 256 + p0 * 4] = tf ? u1 : u0;
            *(float4*)&sA[r * 256 + p1 * 4] = tf ? u0 : u1;
        }
    }
    // ---- load W (N multiple of 128), transpose-pair, swizzled store ----
    {
        const int tf = (lane >> 2) & 1;
        #pragma unroll
        for (int p = 0; p < 4; p++) {
            int n2 = w + p * 16;
            const float* wp = &W[(size_t)(bn + 2 * n2) * 128 + lane * 4];
            float4 a = *(const float4*)wp;
            float4 b = *(const float4*)(wp + 128);
            float4 v0 = make_float4(a.x, b.x, a.y, b.y);   // kp = 2*lane
            float4 v1 = make_float4(a.z, b.z, a.w, b.w);   // kp = 2*lane+1
            int sx = n2 & 31;
            int p0 = (2 * lane + tf) ^ sx;
            int p1 = (2 * lane + 1 - tf) ^ sx;
            *(float4*)&sB[n2 * 256 + p0 * 4] = tf ? v1 : v0;
            *(float4*)&sB[n2 * 256 + p1 * 4] = tf ? v0 : v1;
        }
    }
    __syncthreads();

    // ---- compute ----
    const int wm = w & 3, wn = w >> 2;
    const int tm = lane >> 2, tn = lane & 3;

    const char* sbase = (const char*)smem;
    int PA[4], PB[4];
    #pragma unroll
    for (int i = 0; i < 4; i++) {
        int r = wm * 32 + tm * 4 + i;
        PA[i] = r * 1024 + (((r >> 2) & 7) << 4);
    }
    #pragma unroll
    for (int j = 0; j < 4; j++) {
        int n2 = wn * 16 + tn + 4 * j;
        PB[j] = 131072 + n2 * 1024 + ((n2 & 31) << 4);
    }

    unsigned long long acc[4][4];
    #pragma unroll
    for (int i = 0; i < 4; i++)
        #pragma unroll
        for (int j = 0; j < 4; j++) acc[i][j] = 0ull;

    #pragma unroll
    for (int kp = 0; kp < 64; kp++) {
        const int c = kp << 4;
        ulonglong2 bv[4], av[4];
        #pragma unroll
        for (int j = 0; j < 4; j++)
            bv[j] = *(const ulonglong2*)(sbase + (PB[j] ^ c));
        #pragma unroll
        for (int i = 0; i < 4; i++)
            av[i] = *(const ulonglong2*)(sbase + (PA[i] ^ c));
        #pragma unroll
        for (int i = 0; i < 4; i++)
            #pragma unroll
            for (int j = 0; j < 4; j++) {
                asm("fma.rn.f32x2 %0, %1, %2, %0;"
                    : "+l"(acc[i][j]) : "l"(av[i].x), "l"(bv[j].x));
                asm("fma.rn.f32x2 %0, %1, %2, %0;"
                    : "+l"(acc[i][j]) : "l"(av[i].y), "l"(bv[j].y));
            }
    }

    // ---- epilogue: bias + store ----
    float2 bs[4];
    #pragma unroll
    for (int j = 0; j < 4; j++) {
        int n0 = wn * 32 + 2 * tn + 8 * j;
        bs[j] = *(const float2*)&bias[bn + n0];
    }
    #pragma unroll
    for (int i = 0; i < 4; i++) {
        int m = bm + wm * 32 + tm * 4 + i;
        if (m >= M) continue;
        float* crow = &C[(size_t)m * N + bn];
        #pragma unroll
        for (int j = 0; j < 4; j++) {
            int n0 = wn * 32 + 2 * tn + 8 * j;
            float2 v = *(float2*)&acc[i][j];
            v.x += bs[j].x; v.y += bs[j].y;
            *(float2*)&crow[n0] = v;
        }
    }
}

// ---------------- GRU elementwise update (float4) ---------------------------
__device__ __forceinline__ float sigm(float x) {
    return 1.f / (1.f + __expf(-x));
}
__global__ void gru_update() {
    int idx = blockIdx.x * blockDim.x + threadIdx.x;   // NN*32
    if (idx >= NN * 32) return;
    int n = idx >> 5, c = (idx & 31) * 4;
    const float* gi = d_gi + (size_t)n * 384 + c;
    const float* gh = d_gh + (size_t)n * 384 + c;
    float4 ir = *(const float4*)gi;
    float4 iz = *(const float4*)(gi + 128);
    float4 in = *(const float4*)(gi + 256);
    float4 hr = *(const float4*)gh;
    float4 hz = *(const float4*)(gh + 128);
    float4 hn = *(const float4*)(gh + 256);
    float4 h  = *(const float4*)&d_h[(size_t)n * 128 + c];
    float4 o;
    {
        float r = sigm(ir.x + hr.x), z = sigm(iz.x + hz.x);
        float t = tanhf(in.x + r * hn.x);
        o.x = (1.f - z) * t + z * h.x;
    }
    {
        float r = sigm(ir.y + hr.y), z = sigm(iz.y + hz.y);
        float t = tanhf(in.y + r * hn.y);
        o.y = (1.f - z) * t + z * h.y;
    }
    {
        float r = sigm(ir.z + hr.z), z = sigm(iz.z + hz.z);
        float t = tanhf(in.z + r * hn.z);
        o.z = (1.f - z) * t + z * h.z;
    }
    {
        float r = sigm(ir.w + hr.w), z = sigm(iz.w + hz.w);
        float t = tanhf(in.w + r * hn.w);
        o.w = (1.f - z) * t + z * h.w;
    }
    *(float4*)&d_h[(size_t)n * 128 + c] = o;
}

// ---------------- segment max (two-stage; batch is sorted) ------------------
__global__ void init_gmax() {
    int idx = blockIdx.x * blockDim.x + threadIdx.x;
    if (idx >= NG * H) return;
    ((unsigned int*)d_gmax)[idx] = 0xFF800000u;  // -inf
}

__device__ __forceinline__ void atomicMaxF(float* addr, float val) {
    if (val >= 0.f)
        atomicMax((int*)addr, __float_as_int(val));
    else
        atomicMin((unsigned int*)addr, __float_as_uint(val));
}

#define SEG_NODES 256
__global__ void seg_max2(const int* __restrict__ batch) {
    int j = threadIdx.x;                       // 128 threads = columns
    int n0 = blockIdx.x * SEG_NODES;
    int n1 = n0 + SEG_NODES; if (n1 > NN) n1 = NN;
    int g = __ldg(&batch[n0]);
    float mv = -__int_as_float(0x7F800000);    // -inf
    for (int n = n0; n < n1; n++) {
        int gn = __ldg(&batch[n]);
        if (gn != g) {
            atomicMaxF(&d_gmax[(size_t)g * H + j], mv);
            g = gn;
            mv = -__int_as_float(0x7F800000);
        }
        mv = fmaxf(mv, d_dense[(size_t)n * H + j]);
    }
    atomicMaxF(&d_gmax[(size_t)g * H + j], mv);
}

// ---------------- classifier -------------------------------------------------
__global__ void classify(const float* __restrict__ clfW,
                         const float* __restrict__ clfb,
                         float* __restrict__ out) {
    __shared__ float red[4];
    int g = blockIdx.x;
    int t = threadIdx.x;   // 128
    float v = d_gmax[(size_t)g * H + t] * clfW[t];
    #pragma unroll
    for (int o = 16; o > 0; o >>= 1) v += __shfl_down_sync(0xffffffffu, v, o);
    if ((t & 31) == 0) red[t >> 5] = v;
    __syncthreads();
    if (t == 0) {
        float s = red[0] + red[1] + red[2] + red[3] + clfb[0];
        out[g] = 1.f / (1.f + expf(-s));
    }
}

// ---------------- launch -----------------------------------------------------
extern "C" void kernel_launch(void* const* d_in, const int* in_sizes, int n_in,
                              void* d_out, int out_size) {
    const int*   x       = (const int*)d_in[0];
    const int*   ei      = (const int*)d_in[1];
    const int*   batch   = (const int*)d_in[2];
    const float* emb     = (const float*)d_in[3];
    const float* Wih0    = (const float*)d_in[4];
    const float* Whh0    = (const float*)d_in[5];
    const float* bih0    = (const float*)d_in[6];
    const float* bhh0    = (const float*)d_in[7];
    const float* Wih1    = (const float*)d_in[8];
    const float* Whh1    = (const float*)d_in[9];
    const float* bih1    = (const float*)d_in[10];
    const float* bhh1    = (const float*)d_in[11];
    const float* denseW  = (const float*)d_in[12];
    const float* denseB  = (const float*)d_in[13];
    const float* clfW    = (const float*)d_in[14];
    const float* clfB    = (const float*)d_in[15];
    float* out = (float*)d_out;

    const int SMEM = 196608;  // 128KB sA + 64KB sB
    cudaFuncSetAttribute(gemm_f32x2, cudaFuncAttributeMaxDynamicSharedMemorySize, SMEM);

    float *p_h, *p_agg, *p_gi, *p_gh, *p_dense;
    cudaGetSymbolAddress((void**)&p_h, d_h);
    cudaGetSymbolAddress((void**)&p_agg, d_agg);
    cudaGetSymbolAddress((void**)&p_gi, d_gi);
    cudaGetSymbolAddress((void**)&p_gh, d_gh);
    cudaGetSymbolAddress((void**)&p_dense, d_dense);

    const int T = 256;
    dim3 g_gru((NN + 127) / 128, 3);
    dim3 g_dense((NN + 127) / 128, 1);

    gather_embed<<<(NN * 32 + T - 1) / T, T>>>(x, emb);

    const float* Wih[2] = {Wih0, Wih1};
    const float* Whh[2] = {Whh0, Whh1};
    const float* bih[2] = {bih0, bih1};
    const float* bhh[2] = {bhh0, bhh1};

    for (int layer = 0; layer < 2; layer++) {
        zero_agg<<<(NN * H / 4 + T - 1) / T, T>>>();
        scatter_add<<<(NE * 32 + T - 1) / T, T>>>(ei);
        gemm_f32x2<<<g_gru, 512, SMEM>>>(p_agg, Wih[layer], bih[layer], p_gi, NN, 384);
        gemm_f32x2<<<g_gru, 512, SMEM>>>(p_h, Whh[layer], bhh[layer], p_gh, NN, 384);
        gru_update<<<(NN * 32 + T - 1) / T, T>>>();
    }

    gemm_f32x2<<<g_dense, 512, SMEM>>>(p_h, denseW, denseB, p_dense, NN, 128);

    init_gmax<<<(NG * H + T - 1) / T, T>>>();
    seg_max2<<<(NN + SEG_NODES - 1) / SEG_NODES, 128>>>(batch);
    classify<<<NG, 128>>>(clfW, clfB, out);
}

// round 6
// speedup vs baseline: 3.8569x; 1.3623x over previous
#include <cuda_runtime.h>
#include <cuda_bf16.h>
#include <math.h>
#include <stdint.h>

#define NN 100000
#define NE 1600000
#define H  128
#define NG 128

// ---------------- scratch (device globals; no allocation allowed) ----------
__device__ float d_h[(size_t)NN * H];
__device__ float d_agg[(size_t)NN * H];
__device__ float d_gi[(size_t)NN * 3 * H];
__device__ float d_gh[(size_t)NN * 3 * H];
__device__ float d_dense[(size_t)NN * H];
__device__ float d_gmax[(size_t)NG * H];

// ---------------- helpers ----------------------------------------------------
__device__ __forceinline__ uint32_t smem_u32(const void* p) {
    uint32_t a;
    asm("{ .reg .u64 t; cvta.to.shared.u64 t, %1; cvt.u32.u64 %0, t; }"
        : "=r"(a) : "l"(p));
    return a;
}

#define LDSM_X4(r0, r1, r2, r3, addr)                                       \
    asm volatile("ldmatrix.sync.aligned.m8n8.x4.shared.b16 {%0,%1,%2,%3}, [%4];" \
        : "=r"(r0), "=r"(r1), "=r"(r2), "=r"(r3) : "r"(addr))

#define MMA_BF16(c, a0, a1, a2, a3, b0, b1)                                 \
    asm volatile("mma.sync.aligned.m16n8k16.row.col.f32.bf16.bf16.f32 "     \
        "{%0,%1,%2,%3}, {%4,%5,%6,%7}, {%8,%9}, {%0,%1,%2,%3};"             \
        : "+f"((c)[0]), "+f"((c)[1]), "+f"((c)[2]), "+f"((c)[3])            \
        : "r"(a0), "r"(a1), "r"(a2), "r"(a3), "r"(b0), "r"(b1))

// ---------------- gather: h = emb[x] ---------------------------------------
__global__ void gather_embed(const int* __restrict__ x,
                             const float* __restrict__ emb) {
    int idx = blockIdx.x * blockDim.x + threadIdx.x;
    if (idx >= NN * 32) return;
    int n = idx >> 5, c = idx & 31;
    int tok = x[n];
    float4 v = *(const float4*)&emb[(size_t)tok * H + c * 4];
    *(float4*)&d_h[(size_t)n * H + c * 4] = v;
}

// ---------------- zero agg --------------------------------------------------
__global__ void zero_agg() {
    int idx = blockIdx.x * blockDim.x + threadIdx.x;
    if (idx >= NN * H / 4) return;
    *(float4*)&d_agg[(size_t)idx * 4] = make_float4(0.f, 0.f, 0.f, 0.f);
}

// ---------------- scatter-add: agg[dst] += h[src] (vector red) --------------
__global__ void scatter_add(const int* __restrict__ ei) {
    int idx = blockIdx.x * blockDim.x + threadIdx.x;
    if (idx >= NE * 32) return;
    int e = idx >> 5, c = idx & 31;
    int src = __ldg(&ei[e]);
    int dst = __ldg(&ei[NE + e]);
    float4 v = *(const float4*)&d_h[(size_t)src * H + c * 4];
    float* a = &d_agg[(size_t)dst * H + c * 4];
    asm volatile("red.global.add.v4.f32 [%0], {%1,%2,%3,%4};"
                 :: "l"(a), "f"(v.x), "f"(v.y), "f"(v.z), "f"(v.w)
                 : "memory");
}

// ---------------- bf16-split GEMM via mma.sync (m16n8k16) -------------------
// C[M,N] = A[M,128] @ W[N,128]^T + bias.
// Per CTA: 128x128 output, K=128 resident. fp32 split into bf16 hi+lo;
// 3 passes (AhiBhi + AhiBlo + AloBhi) into fp32 accumulators.
// smem tiles: [128 rows][16 chunks of 16B] (256B row stride, bf16),
// chunk swizzle: phys = chunk ^ (row & 7)  -> conflict-free LDSM & stores.
// Warps: 2(m) x 4(n); warp tile 64x32 = 4x4 m16n8 tiles.

#define OFF_AHI  0
#define OFF_ALO  32768
#define OFF_BHI  65536
#define OFF_BLO  98304
#define GEMM_SMEM 131072

// convert 8 consecutive floats -> 4 packed bf16x2 hi + 4 packed lo
__device__ __forceinline__ void cvt8(const float* f, uint32_t* hh, uint32_t* ll) {
    #pragma unroll
    for (int i = 0; i < 4; i++) {
        __nv_bfloat16 h0 = __float2bfloat16(f[2 * i]);
        __nv_bfloat16 h1 = __float2bfloat16(f[2 * i + 1]);
        __nv_bfloat16 l0 = __float2bfloat16(f[2 * i]     - __bfloat162float(h0));
        __nv_bfloat16 l1 = __float2bfloat16(f[2 * i + 1] - __bfloat162float(h1));
        __nv_bfloat162 hp; hp.x = h0; hp.y = h1;
        __nv_bfloat162 lp; lp.x = l0; lp.y = l1;
        hh[i] = *(uint32_t*)&hp;
        ll[i] = *(uint32_t*)&lp;
    }
}

__global__ void __launch_bounds__(256, 1)
gemm_mma(const float* __restrict__ A, const float* __restrict__ W,
         const float* __restrict__ bias, float* __restrict__ C,
         int M, int N) {
    extern __shared__ char smem[];
    const uint32_t sb = smem_u32(smem);
    const int tid = threadIdx.x, wid = tid >> 5, lane = tid & 31;
    const int bm = blockIdx.x * 128, bn = blockIdx.y * 128;

    // ---- fill smem: A and W tiles, split-converted, swizzled ----
    #pragma unroll
    for (int it = 0; it < 8; it++) {
        int p = tid + it * 256;          // 2048 (row, chunk8) slots
        int row = p >> 4, c8 = p & 15;   // chunk of 8 bf16 = 16B
        int phys = (c8 ^ (row & 7)) * 16;
        float fa[8];
        int m = bm + row;
        if (m < M) {
            *(float4*)&fa[0] = *(const float4*)&A[(size_t)m * 128 + c8 * 8];
            *(float4*)&fa[4] = *(const float4*)&A[(size_t)m * 128 + c8 * 8 + 4];
        } else {
            #pragma unroll
            for (int q = 0; q < 8; q++) fa[q] = 0.f;
        }
        uint32_t hh[4], ll[4];
        cvt8(fa, hh, ll);
        *(uint4*)(smem + OFF_AHI + row * 256 + phys) = make_uint4(hh[0], hh[1], hh[2], hh[3]);
        *(uint4*)(smem + OFF_ALO + row * 256 + phys) = make_uint4(ll[0], ll[1], ll[2], ll[3]);

        float fw[8];
        *(float4*)&fw[0] = *(const float4*)&W[(size_t)(bn + row) * 128 + c8 * 8];
        *(float4*)&fw[4] = *(const float4*)&W[(size_t)(bn + row) * 128 + c8 * 8 + 4];
        cvt8(fw, hh, ll);
        *(uint4*)(smem + OFF_BHI + row * 256 + phys) = make_uint4(hh[0], hh[1], hh[2], hh[3]);
        *(uint4*)(smem + OFF_BLO + row * 256 + phys) = make_uint4(ll[0], ll[1], ll[2], ll[3]);
    }
    __syncthreads();

    // ---- compute ----
    const int wm = wid >> 2, wn = wid & 3;
    const int lrow = lane & 15, lc = lane >> 4;

    float acc[4][4][4];
    #pragma unroll
    for (int i = 0; i < 4; i++)
        #pragma unroll
        for (int j = 0; j < 4; j++)
            #pragma unroll
            for (int q = 0; q < 4; q++) acc[i][j][q] = 0.f;

    const uint32_t abases[3] = {sb + OFF_AHI, sb + OFF_AHI, sb + OFF_ALO};
    const uint32_t bbases[3] = {sb + OFF_BHI, sb + OFF_BLO, sb + OFF_BHI};

    #pragma unroll
    for (int ps = 0; ps < 3; ps++) {
        const uint32_t ab = abases[ps], bb = bbases[ps];
        #pragma unroll
        for (int ks = 0; ks < 8; ks++) {
            const int cidx = 2 * ks + lc;
            uint32_t a[4][4];
            #pragma unroll
            for (int tm = 0; tm < 4; tm++) {
                int r = wm * 64 + tm * 16 + lrow;
                uint32_t addr = ab + r * 256 + ((cidx ^ (r & 7)) << 4);
                LDSM_X4(a[tm][0], a[tm][1], a[tm][2], a[tm][3], addr);
            }
            uint32_t b[2][4];
            #pragma unroll
            for (int u = 0; u < 2; u++) {
                int r = wn * 32 + u * 16 + lrow;
                uint32_t addr = bb + r * 256 + ((cidx ^ (r & 7)) << 4);
                LDSM_X4(b[u][0], b[u][1], b[u][2], b[u][3], addr);
            }
            #pragma unroll
            for (int tm = 0; tm < 4; tm++)
                #pragma unroll
                for (int tn = 0; tn < 4; tn++) {
                    int u = tn >> 1, s = tn & 1;
                    MMA_BF16(acc[tm][tn], a[tm][0], a[tm][1], a[tm][2], a[tm][3],
                             b[u][s], b[u][2 + s]);
                }
        }
    }

    // ---- epilogue: bias + store ----
    const int g = lane >> 2, q = lane & 3;
    #pragma unroll
    for (int tn = 0; tn < 4; tn++) {
        int n = bn + wn * 32 + tn * 8 + q * 2;
        float2 bsv = *(const float2*)&bias[n];
        #pragma unroll
        for (int tm = 0; tm < 4; tm++) {
            int m0 = bm + wm * 64 + tm * 16 + g;
            if (m0 < M) {
                float2 v = make_float2(acc[tm][tn][0] + bsv.x, acc[tm][tn][1] + bsv.y);
                *(float2*)&C[(size_t)m0 * N + n] = v;
            }
            if (m0 + 8 < M) {
                float2 v = make_float2(acc[tm][tn][2] + bsv.x, acc[tm][tn][3] + bsv.y);
                *(float2*)&C[(size_t)(m0 + 8) * N + n] = v;
            }
        }
    }
}

// ---------------- GRU elementwise update (float4) ---------------------------
__device__ __forceinline__ float sigm(float x) {
    return 1.f / (1.f + __expf(-x));
}
__global__ void gru_update() {
    int idx = blockIdx.x * blockDim.x + threadIdx.x;
    if (idx >= NN * 32) return;
    int n = idx >> 5, c = (idx & 31) * 4;
    const float* gi = d_gi + (size_t)n * 384 + c;
    const float* gh = d_gh + (size_t)n * 384 + c;
    float4 ir = *(const float4*)gi;
    float4 iz = *(const float4*)(gi + 128);
    float4 in = *(const float4*)(gi + 256);
    float4 hr = *(const float4*)gh;
    float4 hz = *(const float4*)(gh + 128);
    float4 hn = *(const float4*)(gh + 256);
    float4 h  = *(const float4*)&d_h[(size_t)n * 128 + c];
    float4 o;
    { float r = sigm(ir.x + hr.x), z = sigm(iz.x + hz.x);
      float t = tanhf(in.x + r * hn.x); o.x = (1.f - z) * t + z * h.x; }
    { float r = sigm(ir.y + hr.y), z = sigm(iz.y + hz.y);
      float t = tanhf(in.y + r * hn.y); o.y = (1.f - z) * t + z * h.y; }
    { float r = sigm(ir.z + hr.z), z = sigm(iz.z + hz.z);
      float t = tanhf(in.z + r * hn.z); o.z = (1.f - z) * t + z * h.z; }
    { float r = sigm(ir.w + hr.w), z = sigm(iz.w + hz.w);
      float t = tanhf(in.w + r * hn.w); o.w = (1.f - z) * t + z * h.w; }
    *(float4*)&d_h[(size_t)n * 128 + c] = o;
}

// ---------------- segment max (two-stage; batch is sorted) ------------------
__global__ void init_gmax() {
    int idx = blockIdx.x * blockDim.x + threadIdx.x;
    if (idx >= NG * H) return;
    ((unsigned int*)d_gmax)[idx] = 0xFF800000u;  // -inf
}

__device__ __forceinline__ void atomicMaxF(float* addr, float val) {
    if (val >= 0.f)
        atomicMax((int*)addr, __float_as_int(val));
    else
        atomicMin((unsigned int*)addr, __float_as_uint(val));
}

#define SEG_NODES 256
__global__ void seg_max2(const int* __restrict__ batch) {
    int j = threadIdx.x;
    int n0 = blockIdx.x * SEG_NODES;
    int n1 = n0 + SEG_NODES; if (n1 > NN) n1 = NN;
    int g = __ldg(&batch[n0]);
    float mv = -__int_as_float(0x7F800000);
    for (int n = n0; n < n1; n++) {
        int gn = __ldg(&batch[n]);
        if (gn != g) {
            atomicMaxF(&d_gmax[(size_t)g * H + j], mv);
            g = gn;
            mv = -__int_as_float(0x7F800000);
        }
        mv = fmaxf(mv, d_dense[(size_t)n * H + j]);
    }
    atomicMaxF(&d_gmax[(size_t)g * H + j], mv);
}

// ---------------- classifier -------------------------------------------------
__global__ void classify(const float* __restrict__ clfW,
                         const float* __restrict__ clfb,
                         float* __restrict__ out) {
    __shared__ float red[4];
    int g = blockIdx.x;
    int t = threadIdx.x;
    float v = d_gmax[(size_t)g * H + t] * clfW[t];
    #pragma unroll
    for (int o = 16; o > 0; o >>= 1) v += __shfl_down_sync(0xffffffffu, v, o);
    if ((t & 31) == 0) red[t >> 5] = v;
    __syncthreads();
    if (t == 0) {
        float s = red[0] + red[1] + red[2] + red[3] + clfb[0];
        out[g] = 1.f / (1.f + expf(-s));
    }
}

// ---------------- launch -----------------------------------------------------
extern "C" void kernel_launch(void* const* d_in, const int* in_sizes, int n_in,
                              void* d_out, int out_size) {
    const int*   x       = (const int*)d_in[0];
    const int*   ei      = (const int*)d_in[1];
    const int*   batch   = (const int*)d_in[2];
    const float* emb     = (const float*)d_in[3];
    const float* Wih0    = (const float*)d_in[4];
    const float* Whh0    = (const float*)d_in[5];
    const float* bih0    = (const float*)d_in[6];
    const float* bhh0    = (const float*)d_in[7];
    const float* Wih1    = (const float*)d_in[8];
    const float* Whh1    = (const float*)d_in[9];
    const float* bih1    = (const float*)d_in[10];
    const float* bhh1    = (const float*)d_in[11];
    const float* denseW  = (const float*)d_in[12];
    const float* denseB  = (const float*)d_in[13];
    const float* clfW    = (const float*)d_in[14];
    const float* clfB    = (const float*)d_in[15];
    float* out = (float*)d_out;

    cudaFuncSetAttribute(gemm_mma, cudaFuncAttributeMaxDynamicSharedMemorySize, GEMM_SMEM);

    float *p_h, *p_agg, *p_gi, *p_gh, *p_dense;
    cudaGetSymbolAddress((void**)&p_h, d_h);
    cudaGetSymbolAddress((void**)&p_agg, d_agg);
    cudaGetSymbolAddress((void**)&p_gi, d_gi);
    cudaGetSymbolAddress((void**)&p_gh, d_gh);
    cudaGetSymbolAddress((void**)&p_dense, d_dense);

    const int T = 256;
    dim3 g_gru((NN + 127) / 128, 3);
    dim3 g_dense((NN + 127) / 128, 1);

    gather_embed<<<(NN * 32 + T - 1) / T, T>>>(x, emb);

    const float* Wih[2] = {Wih0, Wih1};
    const float* Whh[2] = {Whh0, Whh1};
    const float* bih[2] = {bih0, bih1};
    const float* bhh[2] = {bhh0, bhh1};

    for (int layer = 0; layer < 2; layer++) {
        zero_agg<<<(NN * H / 4 + T - 1) / T, T>>>();
        scatter_add<<<(NE * 32 + T - 1) / T, T>>>(ei);
        gemm_mma<<<g_gru, 256, GEMM_SMEM>>>(p_agg, Wih[layer], bih[layer], p_gi, NN, 384);
        gemm_mma<<<g_gru, 256, GEMM_SMEM>>>(p_h, Whh[layer], bhh[layer], p_gh, NN, 384);
        gru_update<<<(NN * 32 + T - 1) / T, T>>>();
    }

    gemm_mma<<<g_dense, 256, GEMM_SMEM>>>(p_h, denseW, denseB, p_dense, NN, 128);

    init_gmax<<<(NG * H + T - 1) / T, T>>>();
    seg_max2<<<(NN + SEG_NODES - 1) / SEG_NODES, 128>>>(batch);
    classify<<<NG, 128>>>(clfW, clfB, out);
}

// round 7
// speedup vs baseline: 6.4449x; 1.6710x over previous
#include <cuda_runtime.h>
#include <cuda_bf16.h>
#include <math.h>
#include <stdint.h>

#define NN 100000
#define NE 1600000
#define H  128
#define NG 128
#define NB1 391          // ceil(NN/256)

// ---------------- scratch (device globals) ----------------------------------
__device__ float    d_h[(size_t)NN * H];
__device__ uint32_t d_hhi[(size_t)NN * 64];    // bf16 pairs
__device__ uint32_t d_hlo[(size_t)NN * 64];
__device__ uint32_t d_ahi[(size_t)NN * 64];    // agg hi/lo
__device__ uint32_t d_alo[(size_t)NN * 64];
__device__ float    d_gi[(size_t)NN * 3 * H];
__device__ float    d_gh[(size_t)NN * 3 * H];
__device__ float    d_dense[(size_t)NN * H];
__device__ float    d_gmax[(size_t)NG * H];
// CSR
__device__ int d_cnt[NN];
__device__ int d_rowptr[NN + 1];
__device__ int d_pos[NN];
__device__ int d_esrc[NE];
__device__ int d_bsum[512];
__device__ int d_boff[512];
// pre-split weights: rows 0-383 Wih0, 384-767 Whh0, 768-1151 Wih1,
// 1152-1535 Whh1, 1536-1663 dense   (each row = 128 bf16)
#define WROWS 1664
__device__ __nv_bfloat16 d_whi[(size_t)WROWS * 128];
__device__ __nv_bfloat16 d_wlo[(size_t)WROWS * 128];

// ---------------- helpers ----------------------------------------------------
__device__ __forceinline__ uint32_t smem_u32(const void* p) {
    uint32_t a;
    asm("{ .reg .u64 t; cvta.to.shared.u64 t, %1; cvt.u32.u64 %0, t; }"
        : "=r"(a) : "l"(p));
    return a;
}
#define LDSM_X4(r0, r1, r2, r3, addr)                                       \
    asm volatile("ldmatrix.sync.aligned.m8n8.x4.shared.b16 {%0,%1,%2,%3}, [%4];" \
        : "=r"(r0), "=r"(r1), "=r"(r2), "=r"(r3) : "r"(addr))
#define MMA_BF16(c, a0, a1, a2, a3, b0, b1)                                 \
    asm volatile("mma.sync.aligned.m16n8k16.row.col.f32.bf16.bf16.f32 "     \
        "{%0,%1,%2,%3}, {%4,%5,%6,%7}, {%8,%9}, {%0,%1,%2,%3};"             \
        : "+f"((c)[0]), "+f"((c)[1]), "+f"((c)[2]), "+f"((c)[3])            \
        : "r"(a0), "r"(a1), "r"(a2), "r"(a3), "r"(b0), "r"(b1))
#define CP16(dst, src)                                                      \
    asm volatile("cp.async.cg.shared.global [%0], [%1], 16;"                \
                 :: "r"(dst), "l"(src))
#define CP_COMMIT asm volatile("cp.async.commit_group;")
#define CP_WAIT0  asm volatile("cp.async.wait_group 0;" ::: "memory")

// split float4 -> bf16 hi/lo pairs, store as uint2
__device__ __forceinline__ void split_store(float4 a, uint32_t* hip, uint32_t* lop) {
    __nv_bfloat162 h01 = __floats2bfloat162_rn(a.x, a.y);
    float2 f01 = __bfloat1622float2(h01);
    __nv_bfloat162 l01 = __floats2bfloat162_rn(a.x - f01.x, a.y - f01.y);
    __nv_bfloat162 h23 = __floats2bfloat162_rn(a.z, a.w);
    float2 f23 = __bfloat1622float2(h23);
    __nv_bfloat162 l23 = __floats2bfloat162_rn(a.z - f23.x, a.w - f23.y);
    *(uint2*)hip = make_uint2(*(uint32_t*)&h01, *(uint32_t*)&h23);
    *(uint2*)lop = make_uint2(*(uint32_t*)&l01, *(uint32_t*)&l23);
}

// ---------------- weight pre-split ------------------------------------------
__global__ void conv_weights(const float* __restrict__ Wih0, const float* __restrict__ Whh0,
                             const float* __restrict__ Wih1, const float* __restrict__ Whh1,
                             const float* __restrict__ denseW) {
    int idx = blockIdx.x * blockDim.x + threadIdx.x;   // WROWS*128
    if (idx >= WROWS * 128) return;
    int row = idx >> 7, col = idx & 127;
    float v;
    if      (row < 384)  v = Wih0[row * 128 + col];
    else if (row < 768)  v = Whh0[(row - 384) * 128 + col];
    else if (row < 1152) v = Wih1[(row - 768) * 128 + col];
    else if (row < 1536) v = Whh1[(row - 1152) * 128 + col];
    else                 v = denseW[(row - 1536) * 128 + col];
    __nv_bfloat16 h = __float2bfloat16(v);
    d_whi[idx] = h;
    d_wlo[idx] = __float2bfloat16(v - __bfloat162float(h));
}

// ---------------- gather: h = emb[x] (+ split) ------------------------------
__global__ void gather_embed(const int* __restrict__ x,
                             const float* __restrict__ emb) {
    int idx = blockIdx.x * blockDim.x + threadIdx.x;
    if (idx >= NN * 32) return;
    int n = idx >> 5, c = idx & 31;
    int tok = x[n];
    float4 v = *(const float4*)&emb[(size_t)tok * H + c * 4];
    *(float4*)&d_h[(size_t)n * H + c * 4] = v;
    split_store(v, &d_hhi[(size_t)n * 64 + c * 2], &d_hlo[(size_t)n * 64 + c * 2]);
}

// ---------------- CSR build --------------------------------------------------
__global__ void csr_zero() {
    int i = blockIdx.x * blockDim.x + threadIdx.x;
    if (i < NN) d_cnt[i] = 0;
}
__global__ void csr_hist(const int* __restrict__ ei) {
    int e = blockIdx.x * blockDim.x + threadIdx.x;
    if (e < NE) atomicAdd(&d_cnt[ei[NE + e]], 1);
}
__global__ void csr_bsum() {            // grid NB1, 256 thr
    int tid = threadIdx.x, idx = blockIdx.x * 256 + tid;
    int v = (idx < NN) ? d_cnt[idx] : 0;
    #pragma unroll
    for (int o = 16; o > 0; o >>= 1) v += __shfl_down_sync(0xffffffffu, v, o);
    __shared__ int ws[8];
    if ((tid & 31) == 0) ws[tid >> 5] = v;
    __syncthreads();
    if (tid == 0) {
        int s = 0;
        #pragma unroll
        for (int i = 0; i < 8; i++) s += ws[i];
        d_bsum[blockIdx.x] = s;
    }
}
__global__ void csr_bscan() {           // 1 block, 512 thr
    __shared__ int s[512];
    int t = threadIdx.x;
    int v = (t < NB1) ? d_bsum[t] : 0;
    s[t] = v; __syncthreads();
    for (int o = 1; o < 512; o <<= 1) {
        int x = (t >= o) ? s[t - o] : 0;
        __syncthreads();
        s[t] += x;
        __syncthreads();
    }
    d_boff[t] = s[t] - v;
    if (t == 0) d_rowptr[NN] = NE;
}
__global__ void csr_write() {           // grid NB1, 256 thr
    int tid = threadIdx.x, lane = tid & 31, wid = tid >> 5;
    int idx = blockIdx.x * 256 + tid;
    int v = (idx < NN) ? d_cnt[idx] : 0;
    int incl = v;
    #pragma unroll
    for (int o = 1; o < 32; o <<= 1) {
        int y = __shfl_up_sync(0xffffffffu, incl, o);
        if (lane >= o) incl += y;
    }
    __shared__ int ws[8];
    if (lane == 31) ws[wid] = incl;
    __syncthreads();
    if (tid < 8) {
        int x = ws[tid];
        #pragma unroll
        for (int o = 1; o < 8; o <<= 1) {
            int y = __shfl_up_sync(0xffu, x, o);
            if (tid >= o) x += y;
        }
        ws[tid] = x;
    }
    __syncthreads();
    int base = d_boff[blockIdx.x] + (wid ? ws[wid - 1] : 0);
    int excl = base + incl - v;
    if (idx < NN) { d_rowptr[idx] = excl; d_pos[idx] = excl; }
}
__global__ void csr_fill(const int* __restrict__ ei) {
    int e = blockIdx.x * blockDim.x + threadIdx.x;
    if (e >= NE) return;
    int dst = ei[NE + e];
    int p = atomicAdd(&d_pos[dst], 1);
    d_esrc[p] = ei[e];
}

// ---------------- agg = segment_sum(h[src]) -> bf16 hi/lo -------------------
__global__ void agg_gather() {          // one warp per node
    int gw = (blockIdx.x * blockDim.x + threadIdx.x) >> 5;
    if (gw >= NN) return;
    int lane = threadIdx.x & 31;
    int beg = d_rowptr[gw], end = d_rowptr[gw + 1];
    float4 a0 = make_float4(0.f, 0.f, 0.f, 0.f);
    float4 a1 = make_float4(0.f, 0.f, 0.f, 0.f);
    int i = beg;
    for (; i + 1 < end; i += 2) {
        int s0 = __ldg(&d_esrc[i]), s1 = __ldg(&d_esrc[i + 1]);
        float4 v0 = *(const float4*)&d_h[(size_t)s0 * H + lane * 4];
        float4 v1 = *(const float4*)&d_h[(size_t)s1 * H + lane * 4];
        a0.x += v0.x; a0.y += v0.y; a0.z += v0.z; a0.w += v0.w;
        a1.x += v1.x; a1.y += v1.y; a1.z += v1.z; a1.w += v1.w;
    }
    if (i < end) {
        int s0 = __ldg(&d_esrc[i]);
        float4 v0 = *(const float4*)&d_h[(size_t)s0 * H + lane * 4];
        a0.x += v0.x; a0.y += v0.y; a0.z += v0.z; a0.w += v0.w;
    }
    a0.x += a1.x; a0.y += a1.y; a0.z += a1.z; a0.w += a1.w;
    split_store(a0, &d_ahi[(size_t)gw * 64 + lane * 2], &d_alo[(size_t)gw * 64 + lane * 2]);
}

// ---------------- bf16-split GEMM v2 (pre-split inputs, cp.async) -----------
// C[M,N] = A[M,128] @ W[N,128]^T + bias.  BM=128, BN=64, 256 thr, 2 CTAs/SM.
// smem: Ahi 32K | Alo 32K | Bhi 16K | Blo 16K (row stride 256B, 16-chunk
// swizzle phys = c8 ^ (row&7)).  Warps 4(m) x 2(n); warp tile 32x32.
#define OFF_AHI  0
#define OFF_ALO  32768
#define OFF_BHI  65536
#define OFF_BLO  81920
#define GEMM_SMEM 98304

__global__ void __launch_bounds__(256, 2)
gemm_mma2(const __nv_bfloat16* __restrict__ Ahi, const __nv_bfloat16* __restrict__ Alo,
          const __nv_bfloat16* __restrict__ Whi, const __nv_bfloat16* __restrict__ Wlo,
          const float* __restrict__ bias, float* __restrict__ C, int M, int N) {
    extern __shared__ char smem[];
    const uint32_t sb = smem_u32(smem);
    const int tid = threadIdx.x, wid = tid >> 5, lane = tid & 31;
    const int bm = blockIdx.x * 128, bn = blockIdx.y * 64;

    // ---- async fill ----
    #pragma unroll
    for (int it = 0; it < 8; it++) {
        int p = tid + it * 256;            // 2048 A slots
        int row = p >> 4, c8 = p & 15;
        uint32_t off = row * 256 + ((c8 ^ (row & 7)) << 4);
        int m = bm + row;
        if (m < M) {
            CP16(sb + OFF_AHI + off, Ahi + (size_t)m * 128 + c8 * 8);
            CP16(sb + OFF_ALO + off, Alo + (size_t)m * 128 + c8 * 8);
        } else {
            *(uint4*)(smem + OFF_AHI + off) = make_uint4(0, 0, 0, 0);
            *(uint4*)(smem + OFF_ALO + off) = make_uint4(0, 0, 0, 0);
        }
    }
    #pragma unroll
    for (int it = 0; it < 4; it++) {
        int p = tid + it * 256;            // 1024 B slots
        int row = p >> 4, c8 = p & 15;
        uint32_t off = row * 256 + ((c8 ^ (row & 7)) << 4);
        CP16(sb + OFF_BHI + off, Whi + (size_t)(bn + row) * 128 + c8 * 8);
        CP16(sb + OFF_BLO + off, Wlo + (size_t)(bn + row) * 128 + c8 * 8);
    }
    CP_COMMIT;
    CP_WAIT0;
    __syncthreads();

    // ---- compute ----
    const int wm = wid & 3, wn = wid >> 2;       // 4 x 2 warps
    const int lrow = lane & 15, lc = lane >> 4;

    float acc[2][4][4];
    #pragma unroll
    for (int i = 0; i < 2; i++)
        #pragma unroll
        for (int j = 0; j < 4; j++)
            #pragma unroll
            for (int q = 0; q < 4; q++) acc[i][j][q] = 0.f;

    #pragma unroll
    for (int ks = 0; ks < 8; ks++) {
        const int cidx = 2 * ks + lc;
        uint32_t ah[2][4], al[2][4], bh[2][4], bl[2][4];
        #pragma unroll
        for (int tm = 0; tm < 2; tm++) {
            int r = wm * 32 + tm * 16 + lrow;
            uint32_t off = r * 256 + ((cidx ^ (r & 7)) << 4);
            LDSM_X4(ah[tm][0], ah[tm][1], ah[tm][2], ah[tm][3], sb + OFF_AHI + off);
            LDSM_X4(al[tm][0], al[tm][1], al[tm][2], al[tm][3], sb + OFF_ALO + off);
        }
        #pragma unroll
        for (int u = 0; u < 2; u++) {
            int r = wn * 32 + u * 16 + lrow;
            uint32_t off = r * 256 + ((cidx ^ (r & 7)) << 4);
            LDSM_X4(bh[u][0], bh[u][1], bh[u][2], bh[u][3], sb + OFF_BHI + off);
            LDSM_X4(bl[u][0], bl[u][1], bl[u][2], bl[u][3], sb + OFF_BLO + off);
        }
        #pragma unroll
        for (int tm = 0; tm < 2; tm++)
            #pragma unroll
            for (int tn = 0; tn < 4; tn++) {
                int u = tn >> 1, s = tn & 1;
                MMA_BF16(acc[tm][tn], ah[tm][0], ah[tm][1], ah[tm][2], ah[tm][3],
                         bh[u][s], bh[u][2 + s]);
                MMA_BF16(acc[tm][tn], ah[tm][0], ah[tm][1], ah[tm][2], ah[tm][3],
                         bl[u][s], bl[u][2 + s]);
                MMA_BF16(acc[tm][tn], al[tm][0], al[tm][1], al[tm][2], al[tm][3],
                         bh[u][s], bh[u][2 + s]);
            }
    }

    // ---- epilogue ----
    const int g = lane >> 2, q = lane & 3;
    #pragma unroll
    for (int tn = 0; tn < 4; tn++) {
        int n = bn + wn * 32 + tn * 8 + q * 2;
        float2 bsv = *(const float2*)&bias[n];
        #pragma unroll
        for (int tm = 0; tm < 2; tm++) {
            int m0 = bm + wm * 32 + tm * 16 + g;
            if (m0 < M) {
                float2 v = make_float2(acc[tm][tn][0] + bsv.x, acc[tm][tn][1] + bsv.y);
                *(float2*)&C[(size_t)m0 * N + n] = v;
            }
            if (m0 + 8 < M) {
                float2 v = make_float2(acc[tm][tn][2] + bsv.x, acc[tm][tn][3] + bsv.y);
                *(float2*)&C[(size_t)(m0 + 8) * N + n] = v;
            }
        }
    }
}

// ---------------- GRU elementwise update (+ split h) ------------------------
__device__ __forceinline__ float sigm(float x) {
    return 1.f / (1.f + __expf(-x));
}
__global__ void gru_update() {
    int idx = blockIdx.x * blockDim.x + threadIdx.x;
    if (idx >= NN * 32) return;
    int n = idx >> 5, c = (idx & 31) * 4;
    const float* gi = d_gi + (size_t)n * 384 + c;
    const float* gh = d_gh + (size_t)n * 384 + c;
    float4 ir = *(const float4*)gi;
    float4 iz = *(const float4*)(gi + 128);
    float4 in = *(const float4*)(gi + 256);
    float4 hr = *(const float4*)gh;
    float4 hz = *(const float4*)(gh + 128);
    float4 hn = *(const float4*)(gh + 256);
    float4 h  = *(const float4*)&d_h[(size_t)n * 128 + c];
    float4 o;
    { float r = sigm(ir.x + hr.x), z = sigm(iz.x + hz.x);
      float t = tanhf(in.x + r * hn.x); o.x = (1.f - z) * t + z * h.x; }
    { float r = sigm(ir.y + hr.y), z = sigm(iz.y + hz.y);
      float t = tanhf(in.y + r * hn.y); o.y = (1.f - z) * t + z * h.y; }
    { float r = sigm(ir.z + hr.z), z = sigm(iz.z + hz.z);
      float t = tanhf(in.z + r * hn.z); o.z = (1.f - z) * t + z * h.z; }
    { float r = sigm(ir.w + hr.w), z = sigm(iz.w + hz.w);
      float t = tanhf(in.w + r * hn.w); o.w = (1.f - z) * t + z * h.w; }
    *(float4*)&d_h[(size_t)n * 128 + c] = o;
    split_store(o, &d_hhi[(size_t)n * 64 + c / 2], &d_hlo[(size_t)n * 64 + c / 2]);
}

// ---------------- segment max + classifier ----------------------------------
__global__ void init_gmax() {
    int idx = blockIdx.x * blockDim.x + threadIdx.x;
    if (idx >= NG * H) return;
    ((unsigned int*)d_gmax)[idx] = 0xFF800000u;
}
__device__ __forceinline__ void atomicMaxF(float* addr, float val) {
    if (val >= 0.f)
        atomicMax((int*)addr, __float_as_int(val));
    else
        atomicMin((unsigned int*)addr, __float_as_uint(val));
}
#define SEG_NODES 256
__global__ void seg_max2(const int* __restrict__ batch) {
    int j = threadIdx.x;
    int n0 = blockIdx.x * SEG_NODES;
    int n1 = n0 + SEG_NODES; if (n1 > NN) n1 = NN;
    int g = __ldg(&batch[n0]);
    float mv = -__int_as_float(0x7F800000);
    for (int n = n0; n < n1; n++) {
        int gn = __ldg(&batch[n]);
        if (gn != g) {
            atomicMaxF(&d_gmax[(size_t)g * H + j], mv);
            g = gn;
            mv = -__int_as_float(0x7F800000);
        }
        mv = fmaxf(mv, d_dense[(size_t)n * H + j]);
    }
    atomicMaxF(&d_gmax[(size_t)g * H + j], mv);
}
__global__ void classify(const float* __restrict__ clfW,
                         const float* __restrict__ clfb,
                         float* __restrict__ out) {
    __shared__ float red[4];
    int g = blockIdx.x;
    int t = threadIdx.x;
    float v = d_gmax[(size_t)g * H + t] * clfW[t];
    #pragma unroll
    for (int o = 16; o > 0; o >>= 1) v += __shfl_down_sync(0xffffffffu, v, o);
    if ((t & 31) == 0) red[t >> 5] = v;
    __syncthreads();
    if (t == 0) {
        float s = red[0] + red[1] + red[2] + red[3] + clfb[0];
        out[g] = 1.f / (1.f + expf(-s));
    }
}

// ---------------- launch -----------------------------------------------------
extern "C" void kernel_launch(void* const* d_in, const int* in_sizes, int n_in,
                              void* d_out, int out_size) {
    const int*   x       = (const int*)d_in[0];
    const int*   ei      = (const int*)d_in[1];
    const int*   batch   = (const int*)d_in[2];
    const float* emb     = (const float*)d_in[3];
    const float* Wih0    = (const float*)d_in[4];
    const float* Whh0    = (const float*)d_in[5];
    const float* bih0    = (const float*)d_in[6];
    const float* bhh0    = (const float*)d_in[7];
    const float* Wih1    = (const float*)d_in[8];
    const float* Whh1    = (const float*)d_in[9];
    const float* bih1    = (const float*)d_in[10];
    const float* bhh1    = (const float*)d_in[11];
    const float* denseW  = (const float*)d_in[12];
    const float* denseB  = (const float*)d_in[13];
    const float* clfW    = (const float*)d_in[14];
    const float* clfB    = (const float*)d_in[15];
    float* out = (float*)d_out;

    cudaFuncSetAttribute(gemm_mma2, cudaFuncAttributeMaxDynamicSharedMemorySize, GEMM_SMEM);

    __nv_bfloat16 *p_whi, *p_wlo;
    uint32_t *p_hhi, *p_hlo, *p_ahi, *p_alo;
    float *p_gi, *p_gh, *p_dense;
    cudaGetSymbolAddress((void**)&p_whi, d_whi);
    cudaGetSymbolAddress((void**)&p_wlo, d_wlo);
    cudaGetSymbolAddress((void**)&p_hhi, d_hhi);
    cudaGetSymbolAddress((void**)&p_hlo, d_hlo);
    cudaGetSymbolAddress((void**)&p_ahi, d_ahi);
    cudaGetSymbolAddress((void**)&p_alo, d_alo);
    cudaGetSymbolAddress((void**)&p_gi, d_gi);
    cudaGetSymbolAddress((void**)&p_gh, d_gh);
    cudaGetSymbolAddress((void**)&p_dense, d_dense);

    const int T = 256;
    dim3 g_gru((NN + 127) / 128, 6);    // BN=64, N=384
    dim3 g_dense((NN + 127) / 128, 2);  // N=128

    // weights + embedding gather + CSR build (once per call)
    conv_weights<<<(WROWS * 128 + T - 1) / T, T>>>(Wih0, Whh0, Wih1, Whh1, denseW);
    gather_embed<<<(NN * 32 + T - 1) / T, T>>>(x, emb);
    csr_zero<<<NB1, T>>>();
    csr_hist<<<(NE + T - 1) / T, T>>>(ei);
    csr_bsum<<<NB1, T>>>();
    csr_bscan<<<1, 512>>>();
    csr_write<<<NB1, T>>>();
    csr_fill<<<(NE + T - 1) / T, T>>>(ei);

    const int woff_ih[2] = {0, 768};
    const int woff_hh[2] = {384, 1152};
    const float* bih[2] = {bih0, bih1};
    const float* bhh[2] = {bhh0, bhh1};

    for (int layer = 0; layer < 2; layer++) {
        agg_gather<<<(NN * 32 + T - 1) / T, T>>>();
        gemm_mma2<<<g_gru, T, GEMM_SMEM>>>(
            (const __nv_bfloat16*)p_ahi, (const __nv_bfloat16*)p_alo,
            p_whi + (size_t)woff_ih[layer] * 128, p_wlo + (size_t)woff_ih[layer] * 128,
            bih[layer], p_gi, NN, 384);
        gemm_mma2<<<g_gru, T, GEMM_SMEM>>>(
            (const __nv_bfloat16*)p_hhi, (const __nv_bfloat16*)p_hlo,
            p_whi + (size_t)woff_hh[layer] * 128, p_wlo + (size_t)woff_hh[layer] * 128,
            bhh[layer], p_gh, NN, 384);
        gru_update<<<(NN * 32 + T - 1) / T, T>>>();
    }

    gemm_mma2<<<g_dense, T, GEMM_SMEM>>>(
        (const __nv_bfloat16*)p_hhi, (const __nv_bfloat16*)p_hlo,
        p_whi + (size_t)1536 * 128, p_wlo + (size_t)1536 * 128,
        denseB, p_dense, NN, 128);

    init_gmax<<<(NG * H + T - 1) / T, T>>>();
    seg_max2<<<(NN + SEG_NODES - 1) / SEG_NODES, 128>>>(batch);
    classify<<<NG, 128>>>(clfW, clfB, out);
}

// round 8
// speedup vs baseline: 7.2369x; 1.1229x over previous
#include <cuda_runtime.h>
#include <cuda_bf16.h>
#include <math.h>
#include <stdint.h>

#define NN 100000
#define NE 1600000
#define H  128
#define NG 128
#define NB1 391          // ceil(NN/256)

// ---------------- scratch (device globals) ----------------------------------
__device__ uint32_t d_hhi[(size_t)NN * 64];    // h as bf16 pairs (hi/lo split)
__device__ uint32_t d_hlo[(size_t)NN * 64];
__device__ uint32_t d_ahi[(size_t)NN * 64];    // agg hi/lo
__device__ uint32_t d_alo[(size_t)NN * 64];
__device__ float    d_srz[(size_t)NN * 256];   // i_r+h_r | i_z+h_z (biased)
__device__ float    d_gin[(size_t)NN * 128];   // i_n + bih_n
__device__ float    d_ghn[(size_t)NN * 128];   // h_n + bhh_n
__device__ float    d_gmax[(size_t)NG * H];
// CSR
__device__ int d_cnt[NN];
__device__ int d_rowptr[NN + 1];
__device__ int d_pos[NN];
__device__ int d_esrc[NE];
__device__ int d_bsum[512];
__device__ int d_boff[512];
// pre-split weights: rows 0-383 Wih0, 384-767 Whh0, 768-1151 Wih1,
// 1152-1535 Whh1, 1536-1663 dense
#define WROWS 1664
__device__ __nv_bfloat16 d_whi[(size_t)WROWS * 128];
__device__ __nv_bfloat16 d_wlo[(size_t)WROWS * 128];

// ---------------- helpers ----------------------------------------------------
__device__ __forceinline__ uint32_t smem_u32(const void* p) {
    uint32_t a;
    asm("{ .reg .u64 t; cvta.to.shared.u64 t, %1; cvt.u32.u64 %0, t; }"
        : "=r"(a) : "l"(p));
    return a;
}
#define LDSM_X4(r0, r1, r2, r3, addr)                                       \
    asm volatile("ldmatrix.sync.aligned.m8n8.x4.shared.b16 {%0,%1,%2,%3}, [%4];" \
        : "=r"(r0), "=r"(r1), "=r"(r2), "=r"(r3) : "r"(addr))
#define MMA_BF16(c, a0, a1, a2, a3, b0, b1)                                 \
    asm volatile("mma.sync.aligned.m16n8k16.row.col.f32.bf16.bf16.f32 "     \
        "{%0,%1,%2,%3}, {%4,%5,%6,%7}, {%8,%9}, {%0,%1,%2,%3};"             \
        : "+f"((c)[0]), "+f"((c)[1]), "+f"((c)[2]), "+f"((c)[3])            \
        : "r"(a0), "r"(a1), "r"(a2), "r"(a3), "r"(b0), "r"(b1))
#define CP16(dst, src)                                                      \
    asm volatile("cp.async.cg.shared.global [%0], [%1], 16;"                \
                 :: "r"(dst), "l"(src))
#define CP_COMMIT asm volatile("cp.async.commit_group;")
#define CP_WAIT0  asm volatile("cp.async.wait_group 0;" ::: "memory")
#define NEG_INF __int_as_float(0xFF800000)

// split float4 -> bf16 hi/lo pairs
__device__ __forceinline__ void split_store(float4 a, uint32_t* hip, uint32_t* lop) {
    __nv_bfloat162 h01 = __floats2bfloat162_rn(a.x, a.y);
    float2 f01 = __bfloat1622float2(h01);
    __nv_bfloat162 l01 = __floats2bfloat162_rn(a.x - f01.x, a.y - f01.y);
    __nv_bfloat162 h23 = __floats2bfloat162_rn(a.z, a.w);
    float2 f23 = __bfloat1622float2(h23);
    __nv_bfloat162 l23 = __floats2bfloat162_rn(a.z - f23.x, a.w - f23.y);
    *(uint2*)hip = make_uint2(*(uint32_t*)&h01, *(uint32_t*)&h23);
    *(uint2*)lop = make_uint2(*(uint32_t*)&l01, *(uint32_t*)&l23);
}
// reconstruct 4 floats from hi/lo pairs
__device__ __forceinline__ float4 h_rec(const uint32_t* hip, const uint32_t* lop) {
    uint2 vh = *(const uint2*)hip;
    uint2 vl = *(const uint2*)lop;
    float2 h01 = __bfloat1622float2(*(__nv_bfloat162*)&vh.x);
    float2 h23 = __bfloat1622float2(*(__nv_bfloat162*)&vh.y);
    float2 l01 = __bfloat1622float2(*(__nv_bfloat162*)&vl.x);
    float2 l23 = __bfloat1622float2(*(__nv_bfloat162*)&vl.y);
    return make_float4(h01.x + l01.x, h01.y + l01.y, h23.x + l23.x, h23.y + l23.y);
}

// ---------------- weight pre-split ------------------------------------------
__global__ void conv_weights(const float* __restrict__ Wih0, const float* __restrict__ Whh0,
                             const float* __restrict__ Wih1, const float* __restrict__ Whh1,
                             const float* __restrict__ denseW) {
    int idx = blockIdx.x * blockDim.x + threadIdx.x;
    if (idx >= WROWS * 128) return;
    int row = idx >> 7, col = idx & 127;
    float v;
    if      (row < 384)  v = Wih0[row * 128 + col];
    else if (row < 768)  v = Whh0[(row - 384) * 128 + col];
    else if (row < 1152) v = Wih1[(row - 768) * 128 + col];
    else if (row < 1536) v = Whh1[(row - 1152) * 128 + col];
    else                 v = denseW[(row - 1536) * 128 + col];
    __nv_bfloat16 h = __float2bfloat16(v);
    d_whi[idx] = h;
    d_wlo[idx] = __float2bfloat16(v - __bfloat162float(h));
}

// ---------------- gather: h = emb[x] (split only) ---------------------------
__global__ void gather_embed(const int* __restrict__ x,
                             const float* __restrict__ emb) {
    int idx = blockIdx.x * blockDim.x + threadIdx.x;
    if (idx >= NN * 32) return;
    int n = idx >> 5, c = idx & 31;
    int tok = x[n];
    float4 v = *(const float4*)&emb[(size_t)tok * H + c * 4];
    split_store(v, &d_hhi[(size_t)n * 64 + c * 2], &d_hlo[(size_t)n * 64 + c * 2]);
}

// ---------------- CSR build --------------------------------------------------
__global__ void csr_zero() {
    int i = blockIdx.x * blockDim.x + threadIdx.x;
    if (i < NN) d_cnt[i] = 0;
}
__global__ void csr_hist(const int* __restrict__ ei) {
    int e = blockIdx.x * blockDim.x + threadIdx.x;
    if (e < NE) atomicAdd(&d_cnt[ei[NE + e]], 1);
}
__global__ void csr_bsum() {
    int tid = threadIdx.x, idx = blockIdx.x * 256 + tid;
    int v = (idx < NN) ? d_cnt[idx] : 0;
    #pragma unroll
    for (int o = 16; o > 0; o >>= 1) v += __shfl_down_sync(0xffffffffu, v, o);
    __shared__ int ws[8];
    if ((tid & 31) == 0) ws[tid >> 5] = v;
    __syncthreads();
    if (tid == 0) {
        int s = 0;
        #pragma unroll
        for (int i = 0; i < 8; i++) s += ws[i];
        d_bsum[blockIdx.x] = s;
    }
}
__global__ void csr_bscan() {
    __shared__ int s[512];
    int t = threadIdx.x;
    int v = (t < NB1) ? d_bsum[t] : 0;
    s[t] = v; __syncthreads();
    for (int o = 1; o < 512; o <<= 1) {
        int x = (t >= o) ? s[t - o] : 0;
        __syncthreads();
        s[t] += x;
        __syncthreads();
    }
    d_boff[t] = s[t] - v;
    if (t == 0) d_rowptr[NN] = NE;
}
__global__ void csr_write() {
    int tid = threadIdx.x, lane = tid & 31, wid = tid >> 5;
    int idx = blockIdx.x * 256 + tid;
    int v = (idx < NN) ? d_cnt[idx] : 0;
    int incl = v;
    #pragma unroll
    for (int o = 1; o < 32; o <<= 1) {
        int y = __shfl_up_sync(0xffffffffu, incl, o);
        if (lane >= o) incl += y;
    }
    __shared__ int ws[8];
    if (lane == 31) ws[wid] = incl;
    __syncthreads();
    if (tid < 8) {
        int x = ws[tid];
        #pragma unroll
        for (int o = 1; o < 8; o <<= 1) {
            int y = __shfl_up_sync(0xffu, x, o);
            if (tid >= o) x += y;
        }
        ws[tid] = x;
    }
    __syncthreads();
    int base = d_boff[blockIdx.x] + (wid ? ws[wid - 1] : 0);
    int excl = base + incl - v;
    if (idx < NN) { d_rowptr[idx] = excl; d_pos[idx] = excl; }
}
__global__ void csr_fill(const int* __restrict__ ei) {
    int e = blockIdx.x * blockDim.x + threadIdx.x;
    if (e >= NE) return;
    int dst = ei[NE + e];
    int p = atomicAdd(&d_pos[dst], 1);
    d_esrc[p] = ei[e];
}

// ---------------- agg = segment_sum(h[src]) -> bf16 hi/lo -------------------
__global__ void agg_gather() {          // one warp per node
    int gw = (blockIdx.x * blockDim.x + threadIdx.x) >> 5;
    if (gw >= NN) return;
    int lane = threadIdx.x & 31;
    int beg = d_rowptr[gw], end = d_rowptr[gw + 1];
    float4 a0 = make_float4(0.f, 0.f, 0.f, 0.f);
    float4 a1 = make_float4(0.f, 0.f, 0.f, 0.f);
    int i = beg;
    for (; i + 1 < end; i += 2) {
        int s0 = __ldg(&d_esrc[i]), s1 = __ldg(&d_esrc[i + 1]);
        float4 v0 = h_rec(&d_hhi[(size_t)s0 * 64 + lane * 2], &d_hlo[(size_t)s0 * 64 + lane * 2]);
        float4 v1 = h_rec(&d_hhi[(size_t)s1 * 64 + lane * 2], &d_hlo[(size_t)s1 * 64 + lane * 2]);
        a0.x += v0.x; a0.y += v0.y; a0.z += v0.z; a0.w += v0.w;
        a1.x += v1.x; a1.y += v1.y; a1.z += v1.z; a1.w += v1.w;
    }
    if (i < end) {
        int s0 = __ldg(&d_esrc[i]);
        float4 v0 = h_rec(&d_hhi[(size_t)s0 * 64 + lane * 2], &d_hlo[(size_t)s0 * 64 + lane * 2]);
        a0.x += v0.x; a0.y += v0.y; a0.z += v0.z; a0.w += v0.w;
    }
    a0.x += a1.x; a0.y += a1.y; a0.z += a1.z; a0.w += a1.w;
    split_store(a0, &d_ahi[(size_t)gw * 64 + lane * 2], &d_alo[(size_t)gw * 64 + lane * 2]);
}

// ---------------- GEMM tile machinery (BM=128, BN=64, K=128 resident) -------
#define OFF_AHI  0
#define OFF_ALO  32768
#define OFF_BHI  65536
#define OFF_BLO  81920
#define GEMM_SMEM 98304

__device__ __forceinline__ void tile_load(uint32_t sb, char* smem,
    const __nv_bfloat16* __restrict__ Ahi, const __nv_bfloat16* __restrict__ Alo,
    const __nv_bfloat16* __restrict__ Whi, const __nv_bfloat16* __restrict__ Wlo,
    int bm, int bn, int M, int tid)
{
    #pragma unroll
    for (int it = 0; it < 8; it++) {
        int p = tid + it * 256;
        int row = p >> 4, c8 = p & 15;
        uint32_t off = row * 256 + ((c8 ^ (row & 7)) << 4);
        int m = bm + row;
        if (m < M) {
            CP16(sb + OFF_AHI + off, Ahi + (size_t)m * 128 + c8 * 8);
            CP16(sb + OFF_ALO + off, Alo + (size_t)m * 128 + c8 * 8);
        } else {
            *(uint4*)(smem + OFF_AHI + off) = make_uint4(0, 0, 0, 0);
            *(uint4*)(smem + OFF_ALO + off) = make_uint4(0, 0, 0, 0);
        }
    }
    #pragma unroll
    for (int it = 0; it < 4; it++) {
        int p = tid + it * 256;
        int row = p >> 4, c8 = p & 15;
        uint32_t off = row * 256 + ((c8 ^ (row & 7)) << 4);
        CP16(sb + OFF_BHI + off, Whi + (size_t)(bn + row) * 128 + c8 * 8);
        CP16(sb + OFF_BLO + off, Wlo + (size_t)(bn + row) * 128 + c8 * 8);
    }
    CP_COMMIT;
    CP_WAIT0;
}

__device__ __forceinline__ void tile_compute(uint32_t sb, float acc[2][4][4],
                                             int wm, int wn, int lrow, int lc)
{
    #pragma unroll
    for (int ks = 0; ks < 8; ks++) {
        const int cidx = 2 * ks + lc;
        uint32_t ah[2][4], al[2][4], bh[2][4], bl[2][4];
        #pragma unroll
        for (int tm = 0; tm < 2; tm++) {
            int r = wm * 32 + tm * 16 + lrow;
            uint32_t off = r * 256 + ((cidx ^ (r & 7)) << 4);
            LDSM_X4(ah[tm][0], ah[tm][1], ah[tm][2], ah[tm][3], sb + OFF_AHI + off);
            LDSM_X4(al[tm][0], al[tm][1], al[tm][2], al[tm][3], sb + OFF_ALO + off);
        }
        #pragma unroll
        for (int u = 0; u < 2; u++) {
            int r = wn * 32 + u * 16 + lrow;
            uint32_t off = r * 256 + ((cidx ^ (r & 7)) << 4);
            LDSM_X4(bh[u][0], bh[u][1], bh[u][2], bh[u][3], sb + OFF_BHI + off);
            LDSM_X4(bl[u][0], bl[u][1], bl[u][2], bl[u][3], sb + OFF_BLO + off);
        }
        #pragma unroll
        for (int tm = 0; tm < 2; tm++)
            #pragma unroll
            for (int tn = 0; tn < 4; tn++) {
                int u = tn >> 1, s = tn & 1;
                MMA_BF16(acc[tm][tn], ah[tm][0], ah[tm][1], ah[tm][2], ah[tm][3],
                         bh[u][s], bh[u][2 + s]);
                MMA_BF16(acc[tm][tn], ah[tm][0], ah[tm][1], ah[tm][2], ah[tm][3],
                         bl[u][s], bl[u][2 + s]);
                MMA_BF16(acc[tm][tn], al[tm][0], al[tm][1], al[tm][2], al[tm][3],
                         bh[u][s], bh[u][2 + s]);
            }
    }
}

// ---------------- fused dual GEMM: gi-tile + gh-tile per CTA ----------------
__global__ void __launch_bounds__(256, 2)
gemm_dual(const __nv_bfloat16* __restrict__ Aihi, const __nv_bfloat16* __restrict__ Ailo,
          const __nv_bfloat16* __restrict__ Wihi, const __nv_bfloat16* __restrict__ Wilo,
          const __nv_bfloat16* __restrict__ Ahhi, const __nv_bfloat16* __restrict__ Ahlo,
          const __nv_bfloat16* __restrict__ Whhi, const __nv_bfloat16* __restrict__ Whlo,
          const float* __restrict__ bih, const float* __restrict__ bhh,
          float* __restrict__ srz, float* __restrict__ gin, float* __restrict__ ghn,
          int M)
{
    extern __shared__ char smem[];
    const uint32_t sb = smem_u32(smem);
    const int tid = threadIdx.x, wid = tid >> 5, lane = tid & 31;
    const int bm = blockIdx.x * 128;
    const int bt = blockIdx.y, bn = bt * 64;
    const int wm = wid & 3, wn = wid >> 2;
    const int lrow = lane & 15, lc = lane >> 4;

    float acc_i[2][4][4], acc_h[2][4][4];
    #pragma unroll
    for (int i = 0; i < 2; i++)
        #pragma unroll
        for (int j = 0; j < 4; j++)
            #pragma unroll
            for (int q = 0; q < 4; q++) { acc_i[i][j][q] = 0.f; acc_h[i][j][q] = 0.f; }

    tile_load(sb, smem, Aihi, Ailo, Wihi, Wilo, bm, bn, M, tid);
    __syncthreads();
    tile_compute(sb, acc_i, wm, wn, lrow, lc);
    __syncthreads();                         // everyone done reading phase-0 smem
    tile_load(sb, smem, Ahhi, Ahlo, Whhi, Whlo, bm, bn, M, tid);
    __syncthreads();
    tile_compute(sb, acc_h, wm, wn, lrow, lc);

    // ---- epilogue ----
    const int g = lane >> 2, q = lane & 3;
    if (bt < 4) {                            // r/z gates: write summed
        #pragma unroll
        for (int tn = 0; tn < 4; tn++) {
            int n = bn + wn * 32 + tn * 8 + q * 2;
            float2 b2 = make_float2(bih[n] + bhh[n], bih[n + 1] + bhh[n + 1]);
            #pragma unroll
            for (int tm = 0; tm < 2; tm++) {
                int m0 = bm + wm * 32 + tm * 16 + g;
                if (m0 < M) {
                    float2 v = make_float2(acc_i[tm][tn][0] + acc_h[tm][tn][0] + b2.x,
                                           acc_i[tm][tn][1] + acc_h[tm][tn][1] + b2.y);
                    *(float2*)&srz[(size_t)m0 * 256 + n] = v;
                }
                if (m0 + 8 < M) {
                    float2 v = make_float2(acc_i[tm][tn][2] + acc_h[tm][tn][2] + b2.x,
                                           acc_i[tm][tn][3] + acc_h[tm][tn][3] + b2.y);
                    *(float2*)&srz[(size_t)(m0 + 8) * 256 + n] = v;
                }
            }
        }
    } else {                                 // n gate: write i_n, h_n separately
        int nb = bn - 256;
        #pragma unroll
        for (int tn = 0; tn < 4; tn++) {
            int cl = wn * 32 + tn * 8 + q * 2;
            int ngl = bn + cl;
            float2 bi2 = *(const float2*)&bih[ngl];
            float2 bh2 = *(const float2*)&bhh[ngl];
            #pragma unroll
            for (int tm = 0; tm < 2; tm++) {
                int m0 = bm + wm * 32 + tm * 16 + g;
                if (m0 < M) {
                    *(float2*)&gin[(size_t)m0 * 128 + nb + cl] =
                        make_float2(acc_i[tm][tn][0] + bi2.x, acc_i[tm][tn][1] + bi2.y);
                    *(float2*)&ghn[(size_t)m0 * 128 + nb + cl] =
                        make_float2(acc_h[tm][tn][0] + bh2.x, acc_h[tm][tn][1] + bh2.y);
                }
                if (m0 + 8 < M) {
                    *(float2*)&gin[(size_t)(m0 + 8) * 128 + nb + cl] =
                        make_float2(acc_i[tm][tn][2] + bi2.x, acc_i[tm][tn][3] + bi2.y);
                    *(float2*)&ghn[(size_t)(m0 + 8) * 128 + nb + cl] =
                        make_float2(acc_h[tm][tn][2] + bh2.x, acc_h[tm][tn][3] + bh2.y);
                }
            }
        }
    }
}

// ---------------- GRU elementwise update ------------------------------------
__device__ __forceinline__ float sigm(float x) {
    return 1.f / (1.f + __expf(-x));
}
__global__ void gru_update() {
    int idx = blockIdx.x * blockDim.x + threadIdx.x;
    if (idx >= NN * 32) return;
    int n = idx >> 5, c = idx & 31;
    const float* srz = d_srz + (size_t)n * 256;
    float4 sr = *(const float4*)&srz[c * 4];
    float4 sz = *(const float4*)&srz[128 + c * 4];
    float4 gn = *(const float4*)&d_gin[(size_t)n * 128 + c * 4];
    float4 hn = *(const float4*)&d_ghn[(size_t)n * 128 + c * 4];
    float4 h  = h_rec(&d_hhi[(size_t)n * 64 + c * 2], &d_hlo[(size_t)n * 64 + c * 2]);
    float4 o;
    { float r = sigm(sr.x), z = sigm(sz.x);
      float t = tanhf(gn.x + r * hn.x); o.x = (1.f - z) * t + z * h.x; }
    { float r = sigm(sr.y), z = sigm(sz.y);
      float t = tanhf(gn.y + r * hn.y); o.y = (1.f - z) * t + z * h.y; }
    { float r = sigm(sr.z), z = sigm(sz.z);
      float t = tanhf(gn.z + r * hn.z); o.z = (1.f - z) * t + z * h.z; }
    { float r = sigm(sr.w), z = sigm(sz.w);
      float t = tanhf(gn.w + r * hn.w); o.w = (1.f - z) * t + z * h.w; }
    split_store(o, &d_hhi[(size_t)n * 64 + c * 2], &d_hlo[(size_t)n * 64 + c * 2]);
}

// ---------------- gmax init + atomic max ------------------------------------
__global__ void init_gmax() {
    int idx = blockIdx.x * blockDim.x + threadIdx.x;
    if (idx >= NG * H) return;
    ((unsigned int*)d_gmax)[idx] = 0xFF800000u;
}
__device__ __forceinline__ void atomicMaxF(float* addr, float val) {
    if (val >= 0.f)
        atomicMax((int*)addr, __float_as_int(val));
    else
        atomicMin((unsigned int*)addr, __float_as_uint(val));
}

// ---------------- fused dense GEMM + segment max -----------------------------
__global__ void __launch_bounds__(256, 2)
dense_segmax(const __nv_bfloat16* __restrict__ Ahi, const __nv_bfloat16* __restrict__ Alo,
             const __nv_bfloat16* __restrict__ Whi, const __nv_bfloat16* __restrict__ Wlo,
             const float* __restrict__ bias, const int* __restrict__ batch, int M)
{
    extern __shared__ char smem[];
    const uint32_t sb = smem_u32(smem);
    const int tid = threadIdx.x, wid = tid >> 5, lane = tid & 31;
    const int bm = blockIdx.x * 128, bn = blockIdx.y * 64;
    const int wm = wid & 3, wn = wid >> 2;
    const int lrow = lane & 15, lc = lane >> 4;

    float acc[2][4][4];
    #pragma unroll
    for (int i = 0; i < 2; i++)
        #pragma unroll
        for (int j = 0; j < 4; j++)
            #pragma unroll
            for (int q = 0; q < 4; q++) acc[i][j][q] = 0.f;

    tile_load(sb, smem, Ahi, Alo, Whi, Wlo, bm, bn, M, tid);
    __syncthreads();
    tile_compute(sb, acc, wm, wn, lrow, lc);
    __syncthreads();                         // smem now dead -> reuse for staging

    float* sd = (float*)smem;                // [128][68]
    int* sbatch = (int*)(smem + OFF_BHI);    // [128]
    if (tid < 128) sbatch[tid] = __ldg(&batch[min(bm + tid, M - 1)]);

    const int g = lane >> 2, q = lane & 3;
    #pragma unroll
    for (int tn = 0; tn < 4; tn++) {
        int cl = wn * 32 + tn * 8 + q * 2;
        float2 b2 = *(const float2*)&bias[bn + cl];
        #pragma unroll
        for (int tm = 0; tm < 2; tm++) {
            int r0 = wm * 32 + tm * 16 + g;
            bool v0 = (bm + r0 < M), v1 = (bm + r0 + 8 < M);
            sd[r0 * 68 + cl]           = v0 ? acc[tm][tn][0] + b2.x : NEG_INF;
            sd[r0 * 68 + cl + 1]       = v0 ? acc[tm][tn][1] + b2.y : NEG_INF;
            sd[(r0 + 8) * 68 + cl]     = v1 ? acc[tm][tn][2] + b2.x : NEG_INF;
            sd[(r0 + 8) * 68 + cl + 1] = v1 ? acc[tm][tn][3] + b2.y : NEG_INF;
        }
    }
    __syncthreads();

    // segmented max over 32-row strips (batch is sorted)
    int col = tid & 63, r0 = (tid >> 6) * 32;
    int gcur = sbatch[r0];
    float mv = NEG_INF;
    #pragma unroll 8
    for (int r = r0; r < r0 + 32; r++) {
        int gnext = sbatch[r];
        if (gnext != gcur) {
            atomicMaxF(&d_gmax[(size_t)gcur * H + bn + col], mv);
            gcur = gnext;
            mv = NEG_INF;
        }
        mv = fmaxf(mv, sd[r * 68 + col]);
    }
    atomicMaxF(&d_gmax[(size_t)gcur * H + bn + col], mv);
}

// ---------------- classifier -------------------------------------------------
__global__ void classify(const float* __restrict__ clfW,
                         const float* __restrict__ clfb,
                         float* __restrict__ out) {
    __shared__ float red[4];
    int g = blockIdx.x;
    int t = threadIdx.x;
    float v = d_gmax[(size_t)g * H + t] * clfW[t];
    #pragma unroll
    for (int o = 16; o > 0; o >>= 1) v += __shfl_down_sync(0xffffffffu, v, o);
    if ((t & 31) == 0) red[t >> 5] = v;
    __syncthreads();
    if (t == 0) {
        float s = red[0] + red[1] + red[2] + red[3] + clfb[0];
        out[g] = 1.f / (1.f + expf(-s));
    }
}

// ---------------- launch -----------------------------------------------------
extern "C" void kernel_launch(void* const* d_in, const int* in_sizes, int n_in,
                              void* d_out, int out_size) {
    const int*   x       = (const int*)d_in[0];
    const int*   ei      = (const int*)d_in[1];
    const int*   batch   = (const int*)d_in[2];
    const float* emb     = (const float*)d_in[3];
    const float* Wih0    = (const float*)d_in[4];
    const float* Whh0    = (const float*)d_in[5];
    const float* bih0    = (const float*)d_in[6];
    const float* bhh0    = (const float*)d_in[7];
    const float* Wih1    = (const float*)d_in[8];
    const float* Whh1    = (const float*)d_in[9];
    const float* bih1    = (const float*)d_in[10];
    const float* bhh1    = (const float*)d_in[11];
    const float* denseW  = (const float*)d_in[12];
    const float* denseB  = (const float*)d_in[13];
    const float* clfW    = (const float*)d_in[14];
    const float* clfB    = (const float*)d_in[15];
    float* out = (float*)d_out;

    cudaFuncSetAttribute(gemm_dual, cudaFuncAttributeMaxDynamicSharedMemorySize, GEMM_SMEM);
    cudaFuncSetAttribute(dense_segmax, cudaFuncAttributeMaxDynamicSharedMemorySize, GEMM_SMEM);

    __nv_bfloat16 *p_whi, *p_wlo;
    uint32_t *p_hhi, *p_hlo, *p_ahi, *p_alo;
    float *p_srz, *p_gin, *p_ghn;
    cudaGetSymbolAddress((void**)&p_whi, d_whi);
    cudaGetSymbolAddress((void**)&p_wlo, d_wlo);
    cudaGetSymbolAddress((void**)&p_hhi, d_hhi);
    cudaGetSymbolAddress((void**)&p_hlo, d_hlo);
    cudaGetSymbolAddress((void**)&p_ahi, d_ahi);
    cudaGetSymbolAddress((void**)&p_alo, d_alo);
    cudaGetSymbolAddress((void**)&p_srz, d_srz);
    cudaGetSymbolAddress((void**)&p_gin, d_gin);
    cudaGetSymbolAddress((void**)&p_ghn, d_ghn);

    const int T = 256;
    dim3 g_dual((NN + 127) / 128, 6);
    dim3 g_dense((NN + 127) / 128, 2);

    conv_weights<<<(WROWS * 128 + T - 1) / T, T>>>(Wih0, Whh0, Wih1, Whh1, denseW);
    gather_embed<<<(NN * 32 + T - 1) / T, T>>>(x, emb);
    csr_zero<<<NB1, T>>>();
    csr_hist<<<(NE + T - 1) / T, T>>>(ei);
    csr_bsum<<<NB1, T>>>();
    csr_bscan<<<1, 512>>>();
    csr_write<<<NB1, T>>>();
    csr_fill<<<(NE + T - 1) / T, T>>>(ei);

    const int woff_ih[2] = {0, 768};
    const int woff_hh[2] = {384, 1152};
    const float* bih[2] = {bih0, bih1};
    const float* bhh[2] = {bhh0, bhh1};

    for (int layer = 0; layer < 2; layer++) {
        agg_gather<<<(NN * 32 + T - 1) / T, T>>>();
        gemm_dual<<<g_dual, T, GEMM_SMEM>>>(
            (const __nv_bfloat16*)p_ahi, (const __nv_bfloat16*)p_alo,
            p_whi + (size_t)woff_ih[layer] * 128, p_wlo + (size_t)woff_ih[layer] * 128,
            (const __nv_bfloat16*)p_hhi, (const __nv_bfloat16*)p_hlo,
            p_whi + (size_t)woff_hh[layer] * 128, p_wlo + (size_t)woff_hh[layer] * 128,
            bih[layer], bhh[layer], p_srz, p_gin, p_ghn, NN);
        gru_update<<<(NN * 32 + T - 1) / T, T>>>();
    }

    init_gmax<<<(NG * H + T - 1) / T, T>>>();
    dense_segmax<<<g_dense, T, GEMM_SMEM>>>(
        (const __nv_bfloat16*)p_hhi, (const __nv_bfloat16*)p_hlo,
        p_whi + (size_t)1536 * 128, p_wlo + (size_t)1536 * 128,
        denseB, batch, NN);
    classify<<<NG, 128>>>(clfW, clfB, out);
}